// round 9
// baseline (speedup 1.0000x reference)
#include <cuda_runtime.h>
#include <math.h>
#include <stdint.h>

// Problem constants
#define B   4
#define CIN 256
#define C   128
#define HW  64
#define N   4096          // HW*HW
#define CQK 16
#define ESPLIT 16         // CAM energy split-k slices

// ---------------- scratch (device globals; no allocation) ----------------
__device__ float g_y[B * C * N];        // conv out, then feat (in-place) : 8 MB
__device__ float g_scale[C];
__device__ float g_shift[C];
__device__ float g_bnp0[512];
__device__ float g_bnp1[512];
__device__ uint32_t g_q[B * CQK * N];   // tf32 bits
__device__ uint32_t g_k[B * CQK * N];   // tf32 bits
__device__ uint32_t g_v[B * C * N];     // tf32 bits : 8 MB
__device__ float g_e[B * C * C];        // CAM attn
__device__ float g_ep[ESPLIT * B * C * C];  // CAM energy partials : 4 MB
__device__ uint32_t g_w2hi[9 * 128 * 256];  // conv weights, tf32 hi, [off][co][ci]
__device__ uint32_t g_w2lo[9 * 128 * 256];  // tf32 residual

// ================= base-ISA tensor helpers (NO tcgen05 — plain sm_103) ======
__device__ __forceinline__ uint32_t f32_tf32(float f) {
    uint32_t r;
    asm("cvt.rna.tf32.f32 %0, %1;" : "=r"(r) : "f"(f));
    return r;
}
__device__ __forceinline__ float tanh_ap(float x) {
    float y;
    asm("tanh.approx.f32 %0, %1;" : "=f"(y) : "f"(x));
    return y;
}
// D += A(16x8 tf32) * B(8x8 tf32), fp32 accum
__device__ __forceinline__ void mma_tf32(float* d, const uint32_t* a, uint32_t b0, uint32_t b1) {
    asm volatile(
        "mma.sync.aligned.m16n8k8.row.col.f32.tf32.tf32.f32 "
        "{%0,%1,%2,%3}, {%4,%5,%6,%7}, {%8,%9}, {%0,%1,%2,%3};"
        : "+f"(d[0]), "+f"(d[1]), "+f"(d[2]), "+f"(d[3])
        : "r"(a[0]), "r"(a[1]), "r"(a[2]), "r"(a[3]), "r"(b0), "r"(b1));
}
__device__ __forceinline__ void cp16(uint32_t saddr, const void* g) {
    asm volatile("cp.async.cg.shared.global [%0], [%1], 16;" :: "r"(saddr), "l"(g));
}
__device__ __forceinline__ void cp_commit() {
    asm volatile("cp.async.commit_group;" ::: "memory");
}
template <int NN> __device__ __forceinline__ void cp_wait() {
    asm volatile("cp.async.wait_group %0;" :: "n"(NN) : "memory");
}

// ---------------- K0: weight prep: w -> tf32 hi/lo, [off][co][ci] ------------
__global__ void wprep_kernel(const float* __restrict__ w) {
    int i = blockIdx.x * 256 + threadIdx.x;
    if (i >= 9 * 128 * 256) return;
    int off = i >> 15;
    int rem = i & 32767;
    int co = rem >> 8, ci = rem & 255;
    float v = w[(co * 256 + ci) * 9 + off];
    uint32_t hi = f32_tf32(v);
    g_w2hi[i] = hi;
    g_w2lo[i] = f32_tf32(v - __uint_as_float(hi));
}

// ---------------- K1: 3x3 conv via mma.sync tf32 (3xTF32 split) --------------
// CTA: row y x 128 co.  ci chunk = 16; ALL 9 offsets' weights staged per chunk
// via cp.async -> only 2 barriers per chunk.
#define CXS_HI 0                      // x tile 16ci x (3*66 pad 200) = 3200
#define CXS_LO 3200
#define CWS_HI 6400                   // 9off x 128co x 20(16 ci pad) = 23040
#define CWS_LO 29440
#define CONV_SMEM_WORDS 52480         // 209920 B

__global__ __launch_bounds__(256)
void conv_tc_kernel(const float* __restrict__ x) {
    extern __shared__ uint32_t cs[];
    const int y = blockIdx.x, b = blockIdx.y;
    const int t = threadIdx.x;
    const int w = t >> 5, lane = t & 31;
    const int lq = lane >> 2, lr = lane & 3;
    const int cw = (w >> 1) * 32;     // co base
    const int pw = (w & 1) * 32;      // px base
    const uint32_t sbase = (uint32_t)__cvta_generic_to_shared(cs);

    float acc[2][4][4];
#pragma unroll
    for (int ct = 0; ct < 2; ct++)
#pragma unroll
        for (int nt = 0; nt < 4; nt++)
#pragma unroll
            for (int i = 0; i < 4; i++) acc[ct][nt][i] = 0.f;

#pragma unroll 1
    for (int ci0 = 0; ci0 < CIN; ci0 += 16) {
        __syncthreads();    // all warps done with previous chunk's tiles
        // stage ALL 9 offsets' weights for this ci chunk via cp.async
        for (int g = t; g < 4608; g += 256) {
            int off = g >> 9;           // 512 groups per offset (128co x 4)
            int rem = g & 511;
            int co = rem >> 2, cig = rem & 3;
            uint32_t d = (uint32_t)(off * 2560 + co * 20 + cig * 4);
            int src = (off << 15) + (co << 8) + ci0 + cig * 4;
            cp16(sbase + (CWS_HI + d) * 4, g_w2hi + src);
            cp16(sbase + (CWS_LO + d) * 4, g_w2lo + src);
        }
        // stage x tile (LDG + tf32 hi/lo convert)
        for (int i = t; i < 16 * 198; i += 256) {
            int ci = i / 198, rem = i % 198;
            int yy = rem / 66, xx = rem % 66;
            int gy = y + yy - 1, gx = xx - 1;
            float v = 0.f;
            if (gy >= 0 && gy < HW && gx >= 0 && gx < HW)
                v = x[(((b * CIN + ci0 + ci) << 6) + gy) * 64 + gx];
            uint32_t hi = f32_tf32(v);
            int a = ci * 200 + yy * 66 + xx;
            cs[CXS_HI + a] = hi;
            cs[CXS_LO + a] = f32_tf32(v - __uint_as_float(hi));
        }
        cp_commit();
        cp_wait<0>();
        __syncthreads();

#pragma unroll 1
        for (int off = 0; off < 9; off++) {
            const int ky = off / 3, kx = off % 3;
            const int xb2 = ky * 66 + kx + pw;
            const int wb = off * 2560;
#pragma unroll
            for (int ks = 0; ks < 2; ks++) {
                const int k = ks * 8;
                uint32_t ahi[2][4], alo[2][4];
#pragma unroll
                for (int ct = 0; ct < 2; ct++) {
                    int r = wb + (cw + ct * 16 + lq) * 20 + k + lr;
                    ahi[ct][0] = cs[CWS_HI + r];
                    ahi[ct][1] = cs[CWS_HI + r + 160];
                    ahi[ct][2] = cs[CWS_HI + r + 4];
                    ahi[ct][3] = cs[CWS_HI + r + 164];
                    alo[ct][0] = cs[CWS_LO + r];
                    alo[ct][1] = cs[CWS_LO + r + 160];
                    alo[ct][2] = cs[CWS_LO + r + 4];
                    alo[ct][3] = cs[CWS_LO + r + 164];
                }
#pragma unroll
                for (int nt = 0; nt < 4; nt++) {
                    int a0 = (k + lr) * 200 + xb2 + nt * 8 + lq;
                    int a1 = a0 + 800;
                    uint32_t bh0 = cs[CXS_HI + a0], bh1 = cs[CXS_HI + a1];
                    uint32_t bl0 = cs[CXS_LO + a0], bl1 = cs[CXS_LO + a1];
#pragma unroll
                    for (int ct = 0; ct < 2; ct++) {
                        mma_tf32(acc[ct][nt], ahi[ct], bh0, bh1);
                        mma_tf32(acc[ct][nt], ahi[ct], bl0, bl1);
                        mma_tf32(acc[ct][nt], alo[ct], bh0, bh1);
                    }
                }
            }
        }
    }

#pragma unroll
    for (int ct = 0; ct < 2; ct++) {
#pragma unroll
        for (int rr = 0; rr < 2; rr++) {
            int co = cw + ct * 16 + lq + rr * 8;
            float* row = &g_y[((b * C + co) << 12) + (y << 6) + pw];
#pragma unroll
            for (int nt = 0; nt < 4; nt++) {
                int m = nt * 8 + lr * 2;
                float2 vv;
                vv.x = acc[ct][nt][rr * 2];
                vv.y = acc[ct][nt][rr * 2 + 1];
                *(float2*)&row[m] = vv;
            }
        }
    }
}

// ---------------- K2a: per-(channel,batch) partial stats ----------------
__global__ void bnstats1_kernel() {
    const int blk = blockIdx.x;            // 512 = c*4 + b
    const int c = blk >> 2, b = blk & 3;
    const int t = threadIdx.x;
    const float4* p = (const float4*)&g_y[(b * C + c) << 12];
    float s = 0.f, ss = 0.f;
#pragma unroll
    for (int i = 0; i < 4; i++) {
        float4 v = p[t + i * 256];
        s += v.x + v.y + v.z + v.w;
        ss += v.x * v.x + v.y * v.y + v.z * v.z + v.w * v.w;
    }
    __shared__ float r1[256], r2[256];
    r1[t] = s; r2[t] = ss;
    __syncthreads();
    for (int off = 128; off; off >>= 1) {
        if (t < off) { r1[t] += r1[t + off]; r2[t] += r2[t + off]; }
        __syncthreads();
    }
    if (t == 0) { g_bnp0[blk] = r1[0]; g_bnp1[blk] = r2[0]; }
}

// ---------------- K2b: finalize scale/shift ----------------
__global__ void bnstats2_kernel(const float* __restrict__ gamma, const float* __restrict__ beta) {
    const int c = threadIdx.x;             // 128
    float s = 0.f, ss = 0.f;
#pragma unroll
    for (int b = 0; b < 4; b++) { s += g_bnp0[c * 4 + b]; ss += g_bnp1[c * 4 + b]; }
    const float inv = 1.f / (float)(B * N);
    float mean = s * inv;
    float var  = ss * inv - mean * mean;
    float istd = rsqrtf(var + 1e-5f);
    float sc = gamma[c] * istd;
    g_scale[c] = sc;
    g_shift[c] = beta[c] - mean * sc;
}

// ---------------- K3: BN + ReLU, d_out = 3*feat ----------------
__global__ void bnrelu_kernel(float* __restrict__ out) {
    const int total = B * C * N;
    for (int i = blockIdx.x * 256 + threadIdx.x; i < total; i += 2048 * 256) {
        int c = (i >> 12) & (C - 1);
        float v = fmaxf(g_y[i] * g_scale[c] + g_shift[c], 0.f);
        g_y[i] = v;
        out[i] = 3.f * v;
    }
}

// ---------------- K4: qkv via mma.sync tf32 ----------------------------------
#define QK_WS 0                       // W tf32 [o][c] pitch 132 : 21120 words
#define QK_FS 21120                   // f tf32 [c][n] pitch 72  : 9216 words
#define QK_BIAS 30336                 // 160 floats
#define QK_WORDS 30496

__global__ __launch_bounds__(320)
void qkv_mma_kernel(const float* __restrict__ qw, const float* __restrict__ qb,
                    const float* __restrict__ kw, const float* __restrict__ kb,
                    const float* __restrict__ vw, const float* __restrict__ vb) {
    extern __shared__ uint32_t qs_[];
    const int b = blockIdx.y, n0 = blockIdx.x * 64;
    const int t = threadIdx.x;
    const int w = t >> 5, lane = t & 31;
    const int lq = lane >> 2, lr = lane & 3;

    for (int i = t; i < 160 * 128; i += 320) {
        int o = i >> 7, c = i & 127;
        float wv = (o < 16) ? qw[o * C + c]
                 : (o < 32) ? kw[(o - 16) * C + c]
                            : vw[(o - 32) * C + c];
        qs_[QK_WS + o * 132 + c] = f32_tf32(wv);
    }
    if (t < 160)
        ((float*)(qs_ + QK_BIAS))[t] = (t < 16) ? qb[t] : (t < 32 ? kb[t - 16] : vb[t - 32]);
    for (int i = t; i < 8192; i += 320) {
        int c = i >> 6, n = i & 63;
        qs_[QK_FS + c * 72 + n] = f32_tf32(g_y[((b * C + c) << 12) + n0 + n]);
    }
    __syncthreads();

    const int o0 = w * 16;
    float acc[8][4];
#pragma unroll
    for (int nt = 0; nt < 8; nt++)
#pragma unroll
        for (int i = 0; i < 4; i++) acc[nt][i] = 0.f;

#pragma unroll
    for (int ks = 0; ks < 16; ks++) {
        const int k = ks * 8;
        uint32_t a[4];
        {
            int r = (o0 + lq) * 132 + k + lr;
            a[0] = qs_[QK_WS + r];
            a[1] = qs_[QK_WS + r + 8 * 132];
            a[2] = qs_[QK_WS + r + 4];
            a[3] = qs_[QK_WS + r + 8 * 132 + 4];
        }
#pragma unroll
        for (int nt = 0; nt < 8; nt++) {
            uint32_t b0 = qs_[QK_FS + (k + lr) * 72 + nt * 8 + lq];
            uint32_t b1 = qs_[QK_FS + (k + lr + 4) * 72 + nt * 8 + lq];
            mma_tf32(acc[nt], a, b0, b1);
        }
    }

    const float* bias = (const float*)(qs_ + QK_BIAS);
#pragma unroll
    for (int rr = 0; rr < 2; rr++) {
        int o = o0 + lq + rr * 8;
        float bi = bias[o];
        uint32_t* dst = (o < 16) ? &g_q[((b * CQK + o) << 12) + n0]
                      : (o < 32) ? &g_k[((b * CQK + o - 16) << 12) + n0]
                                 : &g_v[((b * C + o - 32) << 12) + n0];
#pragma unroll
        for (int nt = 0; nt < 8; nt++) {
            int n = nt * 8 + lr * 2;
            uint2 u;
            u.x = f32_tf32(acc[nt][rr * 2] + bi);
            u.y = f32_tf32(acc[nt][rr * 2 + 1] + bi);
            *(uint2*)&dst[n] = u;
        }
    }
}

// ---------------- K5: CAM energy via mma.sync tf32, 3x split, split-k --------
#define CE_FH 0
#define CE_FL 8704
#define CE_WORDS 17408

__global__ __launch_bounds__(256)
void cam_energy_mma_kernel() {
    extern __shared__ uint32_t es[];
    const int b = blockIdx.y, s = blockIdx.x;
    const int nbase = s * (N / ESPLIT);
    const int t = threadIdx.x;
    const int w = t >> 5, lane = t & 31;
    const int lq = lane >> 2, lr = lane & 3;
    const int cw = (w & 3) * 32, dw = (w >> 2) * 64;

    float acc[2][8][4];
#pragma unroll
    for (int ct = 0; ct < 2; ct++)
#pragma unroll
        for (int dt = 0; dt < 8; dt++)
#pragma unroll
            for (int i = 0; i < 4; i++) acc[ct][dt][i] = 0.f;

    for (int it = 0; it < 4; it++) {
        const int n0 = nbase + it * 64;
        __syncthreads();
        for (int i = t; i < 8192; i += 256) {
            int c = i >> 6, n = i & 63;
            float v = g_y[((b * C + c) << 12) + n0 + n];
            uint32_t hi = f32_tf32(v);
            es[CE_FH + c * 68 + n] = hi;
            es[CE_FL + c * 68 + n] = f32_tf32(v - __uint_as_float(hi));
        }
        __syncthreads();

#pragma unroll
        for (int ks = 0; ks < 8; ks++) {
            const int k = ks * 8;
            uint32_t ah[2][4], al[2][4];
#pragma unroll
            for (int ct = 0; ct < 2; ct++) {
                int r = (cw + ct * 16 + lq) * 68 + k + lr;
                ah[ct][0] = es[CE_FH + r];
                ah[ct][1] = es[CE_FH + r + 8 * 68];
                ah[ct][2] = es[CE_FH + r + 4];
                ah[ct][3] = es[CE_FH + r + 8 * 68 + 4];
                al[ct][0] = es[CE_FL + r];
                al[ct][1] = es[CE_FL + r + 8 * 68];
                al[ct][2] = es[CE_FL + r + 4];
                al[ct][3] = es[CE_FL + r + 8 * 68 + 4];
            }
#pragma unroll
            for (int dt = 0; dt < 8; dt++) {
                int rb = (dw + dt * 8 + lq) * 68 + k + lr;
                uint32_t bh0 = es[CE_FH + rb], bh1 = es[CE_FH + rb + 4];
                uint32_t bl0 = es[CE_FL + rb], bl1 = es[CE_FL + rb + 4];
#pragma unroll
                for (int ct = 0; ct < 2; ct++) {
                    mma_tf32(acc[ct][dt], ah[ct], bh0, bh1);
                    mma_tf32(acc[ct][dt], ah[ct], bl0, bl1);
                    mma_tf32(acc[ct][dt], al[ct], bh0, bh1);
                }
            }
        }
    }

    float* ep = &g_ep[(s * B + b) << 14];
#pragma unroll
    for (int ct = 0; ct < 2; ct++) {
#pragma unroll
        for (int rr = 0; rr < 2; rr++) {
            int c = cw + ct * 16 + lq + rr * 8;
#pragma unroll
            for (int dt = 0; dt < 8; dt++) {
                int d = dw + dt * 8 + lr * 2;
                float2 vv;
                vv.x = acc[ct][dt][rr * 2];
                vv.y = acc[ct][dt][rr * 2 + 1];
                *(float2*)&ep[(c << 7) + d] = vv;
            }
        }
    }
}

// ---------------- K6: CAM reduce: sum partials, attn = tanh(rowmax - e) ------
__global__ void cam_reduce_kernel() {
    const int b = blockIdx.y, c = blockIdx.x, t = threadIdx.x; // 128 threads
    float e = 0.f;
#pragma unroll
    for (int s = 0; s < ESPLIT; s++)
        e += g_ep[((s * B + b) << 14) + (c << 7) + t];
    __shared__ float red[128];
    red[t] = e;
    __syncthreads();
    for (int off = 64; off; off >>= 1) {
        if (t < off) red[t] = fmaxf(red[t], red[t + off]);
        __syncthreads();
    }
    g_e[((b * C + c) << 7) + t] = tanhf(red[0] - e);
}

// ---------------- K7: CAM out via mma.sync tf32 ------------------------------
#define CO_AS 0                        // attn tf32 [c][d] pitch 132 : 16896
#define CO_FS 16896                    // f tf32 [d][n] pitch 136    : 17408
#define CO_WORDS 34304

__global__ __launch_bounds__(256)
void cam_out_mma_kernel(const float* __restrict__ gca, float* __restrict__ out) {
    extern __shared__ uint32_t os_[];
    const int b = blockIdx.y, nb = blockIdx.x * 128;
    const int t = threadIdx.x;
    const int w = t >> 5, lane = t & 31;
    const int lq = lane >> 2, lr = lane & 3;
    const int cw = (w & 3) * 32, nw = (w >> 2) * 64;

    for (int i = t; i < 16384; i += 256) {
        int c = i >> 7, d = i & 127;
        os_[CO_AS + c * 132 + d] = f32_tf32(g_e[((b * C + c) << 7) + d]);
    }
    for (int i = t; i < 16384; i += 256) {
        int d = i >> 7, n = i & 127;
        os_[CO_FS + d * 136 + n] = f32_tf32(g_y[((b * C + d) << 12) + nb + n]);
    }
    __syncthreads();

    float acc[2][8][4];
#pragma unroll
    for (int ct = 0; ct < 2; ct++)
#pragma unroll
        for (int nt = 0; nt < 8; nt++)
#pragma unroll
            for (int i = 0; i < 4; i++) acc[ct][nt][i] = 0.f;

#pragma unroll
    for (int ks = 0; ks < 16; ks++) {
        const int k = ks * 8;
        uint32_t a[2][4];
#pragma unroll
        for (int ct = 0; ct < 2; ct++) {
            int r = (cw + ct * 16 + lq) * 132 + k + lr;
            a[ct][0] = os_[CO_AS + r];
            a[ct][1] = os_[CO_AS + r + 8 * 132];
            a[ct][2] = os_[CO_AS + r + 4];
            a[ct][3] = os_[CO_AS + r + 8 * 132 + 4];
        }
#pragma unroll
        for (int nt = 0; nt < 8; nt++) {
            uint32_t b0 = os_[CO_FS + (k + lr) * 136 + nw + nt * 8 + lq];
            uint32_t b1 = os_[CO_FS + (k + lr + 4) * 136 + nw + nt * 8 + lq];
#pragma unroll
            for (int ct = 0; ct < 2; ct++)
                mma_tf32(acc[ct][nt], a[ct], b0, b1);
        }
    }

    const float g = gca[0];
#pragma unroll
    for (int ct = 0; ct < 2; ct++) {
#pragma unroll
        for (int rr = 0; rr < 2; rr++) {
            int c = cw + ct * 16 + lq + rr * 8;
            float* row = &out[((b * C + c) << 12) + nb + nw];
#pragma unroll
            for (int nt = 0; nt < 8; nt++) {
                int n = nt * 8 + lr * 2;
                float2* p = (float2*)&row[n];
                float2 cur = *p;
                cur.x += g * acc[ct][nt][rr * 2];
                cur.y += g * acc[ct][nt][rr * 2 + 1];
                *p = cur;
            }
        }
    }
}

// ---------------- K8: PAM: m-tile 128, n-chunk 64, 3-stage cp.async ----------
#define P_QS 0                       // q^T [m][qc] 128x20 = 2560
#define P_KS 2560                    // k [qc][n]  3 x 16x68 = 3264
#define P_VS 5824                    // v [c][n]   3 x 128x68 = 26112
#define P_SN 31936                   // S^T [n][m] 64x136 = 8704
#define P_WORDS 40640

__global__ __launch_bounds__(256, 1)
void pam_mma_kernel(const float* __restrict__ gpa, float* __restrict__ out) {
    extern __shared__ uint32_t ps[];
    const int b = blockIdx.y, m0 = blockIdx.x * 128;
    const int t = threadIdx.x;
    const int w = t >> 5, lane = t & 31;
    const int lq = lane >> 2, lr = lane & 3;
    const uint32_t sbase = (uint32_t)__cvta_generic_to_shared(ps);

    // stage q^T (tf32 bits)
    for (int i = t; i < 2048; i += 256) {
        int qc = i >> 7, m = i & 127;
        ps[P_QS + m * 20 + qc] = g_q[((b * CQK + qc) << 12) + m0 + m];
    }

    const int krow = t >> 4, kc4 = (t & 15) * 4;
    const uint32_t kdst = sbase + (P_KS + krow * 68 + kc4) * 4;
    const uint32_t* kgsrc = &g_k[((b * CQK + krow) << 12) + kc4];
    const uint32_t vdst = sbase + (P_VS + krow * 68 + kc4) * 4;
    const uint32_t* vgsrc = &g_v[((b * C + krow) << 12) + kc4];

    // prologue: chunks 0 and 1 into slots 0, 1 (separate groups)
    cp16(kdst, kgsrc);
#pragma unroll
    for (int p = 0; p < 8; p++)
        cp16(vdst + p * 16 * 68 * 4, vgsrc + (p << 16));
    cp_commit();
    cp16(kdst + 1088 * 4, kgsrc + 64);
#pragma unroll
    for (int p = 0; p < 8; p++)
        cp16(vdst + (8704 + p * 16 * 68) * 4, vgsrc + (p << 16) + 64);
    cp_commit();

    __syncthreads();   // q^T visible to all warps before fragment hoist

    uint32_t aq[2][4];
#pragma unroll
    for (int ks = 0; ks < 2; ks++) {
        int r = w * 16 + lq, c = ks * 8 + lr;
        aq[ks][0] = ps[P_QS + r * 20 + c];
        aq[ks][1] = ps[P_QS + (r + 8) * 20 + c];
        aq[ks][2] = ps[P_QS + r * 20 + c + 4];
        aq[ks][3] = ps[P_QS + (r + 8) * 20 + c + 4];
    }

    const int cw = (w & 3) * 32, mw = (w >> 2) * 64;
    float acc[2][8][4];
#pragma unroll
    for (int ct = 0; ct < 2; ct++)
#pragma unroll
        for (int mt = 0; mt < 8; mt++)
#pragma unroll
            for (int i = 0; i < 4; i++) acc[ct][mt][i] = 0.f;

    int sc = 0, sp = 2;    // current slot, prefetch slot ((ch+2)%3)
#pragma unroll 1
    for (int ch = 0; ch < 64; ch++) {
        cp_wait<1>();      // chunk ch landed (ch+1 may still be in flight)
        __syncthreads();   // data visibility + all warps past GEMM2(ch-1)

        // prefetch chunk ch+2 into slot sp (last read by GEMM2(ch-1))
        if (ch + 2 < 64) {
            const int n2 = (ch + 2) * 64;
            cp16(kdst + sp * 1088 * 4, kgsrc + n2);
#pragma unroll
            for (int p = 0; p < 8; p++)
                cp16(vdst + (sp * 8704 + p * 16 * 68) * 4, vgsrc + (p << 16) + n2);
        }
        cp_commit();       // always commit (possibly empty) to keep group count

        const uint32_t* ksb = ps + P_KS + sc * 1088;
        const uint32_t* vsb = ps + P_VS + sc * 8704;

        // E phase: warp rows [16w, 16w+16) x 64 n
        float e[8][4];
#pragma unroll
        for (int ni = 0; ni < 8; ni++) {
#pragma unroll
            for (int i = 0; i < 4; i++) e[ni][i] = 0.f;
#pragma unroll
            for (int ks = 0; ks < 2; ks++) {
                uint32_t b0 = ksb[(ks * 8 + lr) * 68 + ni * 8 + lq];
                uint32_t b1 = ksb[(ks * 8 + lr + 4) * 68 + ni * 8 + lq];
                mma_tf32(e[ni], aq[ks], b0, b1);
            }
        }
        {
            int m = w * 16 + lq;
#pragma unroll
            for (int ni = 0; ni < 8; ni++) {
                int n = ni * 8 + lr * 2;
                ps[P_SN + n * 136 + m]           = f32_tf32(tanh_ap(e[ni][0]));
                ps[P_SN + (n + 1) * 136 + m]     = f32_tf32(tanh_ap(e[ni][1]));
                ps[P_SN + n * 136 + m + 8]       = f32_tf32(tanh_ap(e[ni][2]));
                ps[P_SN + (n + 1) * 136 + m + 8] = f32_tf32(tanh_ap(e[ni][3]));
            }
        }
        __syncthreads();   // S^T exchange

        // GEMM2: acc[32c x 64m] += v * S^T
#pragma unroll
        for (int ks = 0; ks < 8; ks++) {
            const int k = ks * 8;
            uint32_t a[2][4], bb[8][2];
#pragma unroll
            for (int ct = 0; ct < 2; ct++) {
                int r = (cw + ct * 16 + lq) * 68 + k + lr;
                a[ct][0] = vsb[r];
                a[ct][1] = vsb[r + 8 * 68];
                a[ct][2] = vsb[r + 4];
                a[ct][3] = vsb[r + 8 * 68 + 4];
            }
#pragma unroll
            for (int mt = 0; mt < 8; mt++) {
                int c = mw + mt * 8 + lq;
                bb[mt][0] = ps[P_SN + (k + lr) * 136 + c];
                bb[mt][1] = ps[P_SN + (k + lr + 4) * 136 + c];
            }
#pragma unroll
            for (int ct = 0; ct < 2; ct++)
#pragma unroll
                for (int mt = 0; mt < 8; mt++)
                    mma_tf32(acc[ct][mt], a[ct], bb[mt][0], bb[mt][1]);
        }

        sc = (sc == 2) ? 0 : sc + 1;
        sp = (sp == 2) ? 0 : sp + 1;
    }

    const float g = gpa[0];
#pragma unroll
    for (int ct = 0; ct < 2; ct++) {
#pragma unroll
        for (int rr = 0; rr < 2; rr++) {
            int c = cw + ct * 16 + lq + rr * 8;
            float* row = &out[((b * C + c) << 12) + m0 + mw];
#pragma unroll
            for (int mt = 0; mt < 8; mt++) {
                int m = mt * 8 + lr * 2;
                float2* p = (float2*)&row[m];
                float2 cur = *p;
                cur.x += g * acc[ct][mt][rr * 2];
                cur.y += g * acc[ct][mt][rr * 2 + 1];
                *p = cur;
            }
        }
    }
}

// ---------------- launch ----------------
extern "C" void kernel_launch(void* const* d_in, const int* in_sizes, int n_in,
                              void* d_out, int out_size) {
    const float* x       = (const float*)d_in[0];
    const float* conv_w  = (const float*)d_in[1];
    const float* bn_g    = (const float*)d_in[2];
    const float* bn_b    = (const float*)d_in[3];
    const float* q_w     = (const float*)d_in[4];
    const float* q_b     = (const float*)d_in[5];
    const float* k_w     = (const float*)d_in[6];
    const float* k_b     = (const float*)d_in[7];
    const float* v_w     = (const float*)d_in[8];
    const float* v_b     = (const float*)d_in[9];
    const float* gca     = (const float*)d_in[10];
    const float* gpa     = (const float*)d_in[11];
    float* out = (float*)d_out;

    cudaFuncSetAttribute(conv_tc_kernel, cudaFuncAttributeMaxDynamicSharedMemorySize,
                         CONV_SMEM_WORDS * 4);
    cudaFuncSetAttribute(pam_mma_kernel, cudaFuncAttributeMaxDynamicSharedMemorySize,
                         P_WORDS * 4);
    cudaFuncSetAttribute(qkv_mma_kernel, cudaFuncAttributeMaxDynamicSharedMemorySize,
                         QK_WORDS * 4);
    cudaFuncSetAttribute(cam_energy_mma_kernel, cudaFuncAttributeMaxDynamicSharedMemorySize,
                         CE_WORDS * 4);
    cudaFuncSetAttribute(cam_out_mma_kernel, cudaFuncAttributeMaxDynamicSharedMemorySize,
                         CO_WORDS * 4);

    wprep_kernel<<<1152, 256>>>(conv_w);
    conv_tc_kernel<<<dim3(64, B), 256, CONV_SMEM_WORDS * 4>>>(x);
    bnstats1_kernel<<<512, 256>>>();
    bnstats2_kernel<<<1, 128>>>(bn_g, bn_b);
    bnrelu_kernel<<<2048, 256>>>(out);
    qkv_mma_kernel<<<dim3(64, B), 320, QK_WORDS * 4>>>(q_w, q_b, k_w, k_b, v_w, v_b);
    cam_energy_mma_kernel<<<dim3(ESPLIT, B), 256, CE_WORDS * 4>>>();
    cam_reduce_kernel<<<dim3(C, B), 128>>>();
    cam_out_mma_kernel<<<dim3(32, B), 256, CO_WORDS * 4>>>(gca, out);
    pam_mma_kernel<<<dim3(32, B), 256, P_WORDS * 4>>>(gpa, out);
}

// round 10
// speedup vs baseline: 1.0620x; 1.0620x over previous
#include <cuda_runtime.h>
#include <math.h>
#include <stdint.h>

// Problem constants
#define B   4
#define CIN 256
#define C   128
#define HW  64
#define N   4096          // HW*HW
#define CQK 16
#define ESPLIT 16         // CAM energy split-k slices

// ---------------- scratch (device globals; no allocation) ----------------
__device__ float g_y[B * C * N];        // conv out, then feat (in-place) : 8 MB
__device__ float g_scale[C];
__device__ float g_shift[C];
__device__ float g_bnp0[512];
__device__ float g_bnp1[512];
__device__ uint32_t g_q[B * CQK * N];   // tf32 bits
__device__ uint32_t g_k[B * CQK * N];   // tf32 bits
__device__ uint32_t g_v[B * C * N];     // tf32 bits : 8 MB
__device__ float g_e[B * C * C];        // CAM attn
__device__ float g_ep[ESPLIT * B * C * C];  // CAM energy partials : 4 MB
__device__ uint32_t g_w2hi[9 * 128 * 256];  // conv weights, tf32 hi, [off][co][ci]
__device__ uint32_t g_w2lo[9 * 128 * 256];  // tf32 residual

// ================= base-ISA tensor helpers (NO tcgen05 — plain sm_103) ======
__device__ __forceinline__ uint32_t f32_tf32(float f) {
    uint32_t r;
    asm("cvt.rna.tf32.f32 %0, %1;" : "=r"(r) : "f"(f));
    return r;
}
__device__ __forceinline__ float tanh_ap(float x) {
    float y;
    asm("tanh.approx.f32 %0, %1;" : "=f"(y) : "f"(x));
    return y;
}
// D += A(16x8 tf32) * B(8x8 tf32), fp32 accum
__device__ __forceinline__ void mma_tf32(float* d, const uint32_t* a, uint32_t b0, uint32_t b1) {
    asm volatile(
        "mma.sync.aligned.m16n8k8.row.col.f32.tf32.tf32.f32 "
        "{%0,%1,%2,%3}, {%4,%5,%6,%7}, {%8,%9}, {%0,%1,%2,%3};"
        : "+f"(d[0]), "+f"(d[1]), "+f"(d[2]), "+f"(d[3])
        : "r"(a[0]), "r"(a[1]), "r"(a[2]), "r"(a[3]), "r"(b0), "r"(b1));
}
__device__ __forceinline__ void cp16(uint32_t saddr, const void* g) {
    asm volatile("cp.async.cg.shared.global [%0], [%1], 16;" :: "r"(saddr), "l"(g));
}
__device__ __forceinline__ void cp_commit() {
    asm volatile("cp.async.commit_group;" ::: "memory");
}
template <int NN> __device__ __forceinline__ void cp_wait() {
    asm volatile("cp.async.wait_group %0;" :: "n"(NN) : "memory");
}

// ---------------- K0: weight prep: w -> tf32 hi/lo, [off][co][ci] ------------
__global__ void wprep_kernel(const float* __restrict__ w) {
    int i = blockIdx.x * 256 + threadIdx.x;
    if (i >= 9 * 128 * 256) return;
    int off = i >> 15;
    int rem = i & 32767;
    int co = rem >> 8, ci = rem & 255;
    float v = w[(co * 256 + ci) * 9 + off];
    uint32_t hi = f32_tf32(v);
    g_w2hi[i] = hi;
    g_w2lo[i] = f32_tf32(v - __uint_as_float(hi));
}

// ---------------- K1: 3x3 conv via mma.sync tf32 (3xTF32 split) --------------
// R8 version: 88 KB smem -> 2 CTAs/SM -> single wave for grid 256.
#define XS_HI 0
#define XS_LO 6400
#define WS_HI 12800
#define WS_LO 17408
#define CONV_SMEM_WORDS 22016

__global__ __launch_bounds__(256)
void conv_tc_kernel(const float* __restrict__ x) {
    extern __shared__ uint32_t cs[];
    const int y = blockIdx.x, b = blockIdx.y;
    const int t = threadIdx.x;
    const int w = t >> 5, lane = t & 31;
    const int lq = lane >> 2, lr = lane & 3;
    const int cw = (w >> 1) * 32;
    const int pw = (w & 1) * 32;

    float acc[2][4][4];
#pragma unroll
    for (int ct = 0; ct < 2; ct++)
#pragma unroll
        for (int nt = 0; nt < 4; nt++)
#pragma unroll
            for (int i = 0; i < 4; i++) acc[ct][nt][i] = 0.f;

    for (int ci0 = 0; ci0 < CIN; ci0 += 32) {
        __syncthreads();
        for (int i = t; i < 32 * 198; i += 256) {
            int ci = i / 198, rem = i % 198;
            int yy = rem / 66, xx = rem % 66;
            int gy = y + yy - 1, gx = xx - 1;
            float v = 0.f;
            if (gy >= 0 && gy < HW && gx >= 0 && gx < HW)
                v = x[(((b * CIN + ci0 + ci) << 6) + gy) * 64 + gx];
            uint32_t hi = f32_tf32(v);
            int a = ci * 200 + yy * 66 + xx;
            cs[XS_HI + a] = hi;
            cs[XS_LO + a] = f32_tf32(v - __uint_as_float(hi));
        }

#pragma unroll 1
        for (int off = 0; off < 9; off++) {
            __syncthreads();
            {
                int base = (off << 15) + ci0;
#pragma unroll
                for (int p = 0; p < 16; p++) {
                    int i = t + p * 256;
                    int co = i >> 5, ci = i & 31;
                    int src = base + (co << 8) + ci;
                    cs[WS_HI + co * 36 + ci] = g_w2hi[src];
                    cs[WS_LO + co * 36 + ci] = g_w2lo[src];
                }
            }
            __syncthreads();
            const int ky = off / 3, kx = off % 3;
            const int xbase = ky * 66 + kx + pw;

#pragma unroll
            for (int ks = 0; ks < 4; ks++) {
                int k = ks * 8;
                uint32_t ahi[2][4], alo[2][4];
#pragma unroll
                for (int ct = 0; ct < 2; ct++) {
                    int r = (cw + ct * 16 + lq) * 36 + k + lr;
                    ahi[ct][0] = cs[WS_HI + r];
                    ahi[ct][1] = cs[WS_HI + r + 8 * 36];
                    ahi[ct][2] = cs[WS_HI + r + 4];
                    ahi[ct][3] = cs[WS_HI + r + 8 * 36 + 4];
                    alo[ct][0] = cs[WS_LO + r];
                    alo[ct][1] = cs[WS_LO + r + 8 * 36];
                    alo[ct][2] = cs[WS_LO + r + 4];
                    alo[ct][3] = cs[WS_LO + r + 8 * 36 + 4];
                }
#pragma unroll
                for (int nt = 0; nt < 4; nt++) {
                    int a0 = (k + lr) * 200 + xbase + nt * 8 + lq;
                    int a1 = a0 + 4 * 200;
                    uint32_t bh0 = cs[XS_HI + a0], bh1 = cs[XS_HI + a1];
                    uint32_t bl0 = cs[XS_LO + a0], bl1 = cs[XS_LO + a1];
#pragma unroll
                    for (int ct = 0; ct < 2; ct++) {
                        mma_tf32(acc[ct][nt], ahi[ct], bh0, bh1);
                        mma_tf32(acc[ct][nt], ahi[ct], bl0, bl1);
                        mma_tf32(acc[ct][nt], alo[ct], bh0, bh1);
                    }
                }
            }
        }
    }

#pragma unroll
    for (int ct = 0; ct < 2; ct++) {
#pragma unroll
        for (int rr = 0; rr < 2; rr++) {
            int co = cw + ct * 16 + lq + rr * 8;
            float* row = &g_y[((b * C + co) << 12) + (y << 6) + pw];
#pragma unroll
            for (int nt = 0; nt < 4; nt++) {
                int m = nt * 8 + lr * 2;
                float2 vv;
                vv.x = acc[ct][nt][rr * 2];
                vv.y = acc[ct][nt][rr * 2 + 1];
                *(float2*)&row[m] = vv;
            }
        }
    }
}

// ---------------- K2a: per-(channel,batch) partial stats ----------------
__global__ void bnstats1_kernel() {
    const int blk = blockIdx.x;            // 512 = c*4 + b
    const int c = blk >> 2, b = blk & 3;
    const int t = threadIdx.x;
    const float4* p = (const float4*)&g_y[(b * C + c) << 12];
    float s = 0.f, ss = 0.f;
#pragma unroll
    for (int i = 0; i < 4; i++) {
        float4 v = p[t + i * 256];
        s += v.x + v.y + v.z + v.w;
        ss += v.x * v.x + v.y * v.y + v.z * v.z + v.w * v.w;
    }
    __shared__ float r1[256], r2[256];
    r1[t] = s; r2[t] = ss;
    __syncthreads();
    for (int off = 128; off; off >>= 1) {
        if (t < off) { r1[t] += r1[t + off]; r2[t] += r2[t + off]; }
        __syncthreads();
    }
    if (t == 0) { g_bnp0[blk] = r1[0]; g_bnp1[blk] = r2[0]; }
}

// ---------------- K2b: finalize scale/shift ----------------
__global__ void bnstats2_kernel(const float* __restrict__ gamma, const float* __restrict__ beta) {
    const int c = threadIdx.x;             // 128
    float s = 0.f, ss = 0.f;
#pragma unroll
    for (int b = 0; b < 4; b++) { s += g_bnp0[c * 4 + b]; ss += g_bnp1[c * 4 + b]; }
    const float inv = 1.f / (float)(B * N);
    float mean = s * inv;
    float var  = ss * inv - mean * mean;
    float istd = rsqrtf(var + 1e-5f);
    float sc = gamma[c] * istd;
    g_scale[c] = sc;
    g_shift[c] = beta[c] - mean * sc;
}

// ---------------- K3: BN + ReLU, d_out = 3*feat ----------------
__global__ void bnrelu_kernel(float* __restrict__ out) {
    const int total = B * C * N;
    for (int i = blockIdx.x * 256 + threadIdx.x; i < total; i += 2048 * 256) {
        int c = (i >> 12) & (C - 1);
        float v = fmaxf(g_y[i] * g_scale[c] + g_shift[c], 0.f);
        g_y[i] = v;
        out[i] = 3.f * v;
    }
}

// ---------------- K4: qkv via mma.sync tf32 ----------------------------------
#define QK_WS 0                       // W tf32 [o][c] pitch 132 : 21120 words
#define QK_FS 21120                   // f tf32 [c][n] pitch 72  : 9216 words
#define QK_BIAS 30336                 // 160 floats
#define QK_WORDS 30496

__global__ __launch_bounds__(320)
void qkv_mma_kernel(const float* __restrict__ qw, const float* __restrict__ qb,
                    const float* __restrict__ kw, const float* __restrict__ kb,
                    const float* __restrict__ vw, const float* __restrict__ vb) {
    extern __shared__ uint32_t qs_[];
    const int b = blockIdx.y, n0 = blockIdx.x * 64;
    const int t = threadIdx.x;
    const int w = t >> 5, lane = t & 31;
    const int lq = lane >> 2, lr = lane & 3;

    for (int i = t; i < 160 * 128; i += 320) {
        int o = i >> 7, c = i & 127;
        float wv = (o < 16) ? qw[o * C + c]
                 : (o < 32) ? kw[(o - 16) * C + c]
                            : vw[(o - 32) * C + c];
        qs_[QK_WS + o * 132 + c] = f32_tf32(wv);
    }
    if (t < 160)
        ((float*)(qs_ + QK_BIAS))[t] = (t < 16) ? qb[t] : (t < 32 ? kb[t - 16] : vb[t - 32]);
    for (int i = t; i < 8192; i += 320) {
        int c = i >> 6, n = i & 63;
        qs_[QK_FS + c * 72 + n] = f32_tf32(g_y[((b * C + c) << 12) + n0 + n]);
    }
    __syncthreads();

    const int o0 = w * 16;
    float acc[8][4];
#pragma unroll
    for (int nt = 0; nt < 8; nt++)
#pragma unroll
        for (int i = 0; i < 4; i++) acc[nt][i] = 0.f;

#pragma unroll
    for (int ks = 0; ks < 16; ks++) {
        const int k = ks * 8;
        uint32_t a[4];
        {
            int r = (o0 + lq) * 132 + k + lr;
            a[0] = qs_[QK_WS + r];
            a[1] = qs_[QK_WS + r + 8 * 132];
            a[2] = qs_[QK_WS + r + 4];
            a[3] = qs_[QK_WS + r + 8 * 132 + 4];
        }
#pragma unroll
        for (int nt = 0; nt < 8; nt++) {
            uint32_t b0 = qs_[QK_FS + (k + lr) * 72 + nt * 8 + lq];
            uint32_t b1 = qs_[QK_FS + (k + lr + 4) * 72 + nt * 8 + lq];
            mma_tf32(acc[nt], a, b0, b1);
        }
    }

    const float* bias = (const float*)(qs_ + QK_BIAS);
#pragma unroll
    for (int rr = 0; rr < 2; rr++) {
        int o = o0 + lq + rr * 8;
        float bi = bias[o];
        uint32_t* dst = (o < 16) ? &g_q[((b * CQK + o) << 12) + n0]
                      : (o < 32) ? &g_k[((b * CQK + o - 16) << 12) + n0]
                                 : &g_v[((b * C + o - 32) << 12) + n0];
#pragma unroll
        for (int nt = 0; nt < 8; nt++) {
            int n = nt * 8 + lr * 2;
            uint2 u;
            u.x = f32_tf32(acc[nt][rr * 2] + bi);
            u.y = f32_tf32(acc[nt][rr * 2 + 1] + bi);
            *(uint2*)&dst[n] = u;
        }
    }
}

// ---------------- K5: CAM energy via mma.sync tf32, 3x split, split-k --------
#define CE_FH 0
#define CE_FL 8704
#define CE_WORDS 17408

__global__ __launch_bounds__(256)
void cam_energy_mma_kernel() {
    extern __shared__ uint32_t es[];
    const int b = blockIdx.y, s = blockIdx.x;
    const int nbase = s * (N / ESPLIT);
    const int t = threadIdx.x;
    const int w = t >> 5, lane = t & 31;
    const int lq = lane >> 2, lr = lane & 3;
    const int cw = (w & 3) * 32, dw = (w >> 2) * 64;

    float acc[2][8][4];
#pragma unroll
    for (int ct = 0; ct < 2; ct++)
#pragma unroll
        for (int dt = 0; dt < 8; dt++)
#pragma unroll
            for (int i = 0; i < 4; i++) acc[ct][dt][i] = 0.f;

    for (int it = 0; it < 4; it++) {
        const int n0 = nbase + it * 64;
        __syncthreads();
        for (int i = t; i < 8192; i += 256) {
            int c = i >> 6, n = i & 63;
            float v = g_y[((b * C + c) << 12) + n0 + n];
            uint32_t hi = f32_tf32(v);
            es[CE_FH + c * 68 + n] = hi;
            es[CE_FL + c * 68 + n] = f32_tf32(v - __uint_as_float(hi));
        }
        __syncthreads();

#pragma unroll
        for (int ks = 0; ks < 8; ks++) {
            const int k = ks * 8;
            uint32_t ah[2][4], al[2][4];
#pragma unroll
            for (int ct = 0; ct < 2; ct++) {
                int r = (cw + ct * 16 + lq) * 68 + k + lr;
                ah[ct][0] = es[CE_FH + r];
                ah[ct][1] = es[CE_FH + r + 8 * 68];
                ah[ct][2] = es[CE_FH + r + 4];
                ah[ct][3] = es[CE_FH + r + 8 * 68 + 4];
                al[ct][0] = es[CE_FL + r];
                al[ct][1] = es[CE_FL + r + 8 * 68];
                al[ct][2] = es[CE_FL + r + 4];
                al[ct][3] = es[CE_FL + r + 8 * 68 + 4];
            }
#pragma unroll
            for (int dt = 0; dt < 8; dt++) {
                int rb = (dw + dt * 8 + lq) * 68 + k + lr;
                uint32_t bh0 = es[CE_FH + rb], bh1 = es[CE_FH + rb + 4];
                uint32_t bl0 = es[CE_FL + rb], bl1 = es[CE_FL + rb + 4];
#pragma unroll
                for (int ct = 0; ct < 2; ct++) {
                    mma_tf32(acc[ct][dt], ah[ct], bh0, bh1);
                    mma_tf32(acc[ct][dt], ah[ct], bl0, bl1);
                    mma_tf32(acc[ct][dt], al[ct], bh0, bh1);
                }
            }
        }
    }

    float* ep = &g_ep[(s * B + b) << 14];
#pragma unroll
    for (int ct = 0; ct < 2; ct++) {
#pragma unroll
        for (int rr = 0; rr < 2; rr++) {
            int c = cw + ct * 16 + lq + rr * 8;
#pragma unroll
            for (int dt = 0; dt < 8; dt++) {
                int d = dw + dt * 8 + lr * 2;
                float2 vv;
                vv.x = acc[ct][dt][rr * 2];
                vv.y = acc[ct][dt][rr * 2 + 1];
                *(float2*)&ep[(c << 7) + d] = vv;
            }
        }
    }
}

// ---------------- K6: CAM reduce: sum partials, attn = tanh(rowmax - e) ------
__global__ void cam_reduce_kernel() {
    const int b = blockIdx.y, c = blockIdx.x, t = threadIdx.x; // 128 threads
    float e = 0.f;
#pragma unroll
    for (int s = 0; s < ESPLIT; s++)
        e += g_ep[((s * B + b) << 14) + (c << 7) + t];
    __shared__ float red[128];
    red[t] = e;
    __syncthreads();
    for (int off = 64; off; off >>= 1) {
        if (t < off) red[t] = fmaxf(red[t], red[t + off]);
        __syncthreads();
    }
    g_e[((b * C + c) << 7) + t] = tanhf(red[0] - e);
}

// ---------------- K7: CAM out via mma.sync tf32 ------------------------------
#define CO_AS 0                        // attn tf32 [c][d] pitch 132 : 16896
#define CO_FS 16896                    // f tf32 [d][n] pitch 136    : 17408
#define CO_WORDS 34304

__global__ __launch_bounds__(256)
void cam_out_mma_kernel(const float* __restrict__ gca, float* __restrict__ out) {
    extern __shared__ uint32_t os_[];
    const int b = blockIdx.y, nb = blockIdx.x * 128;
    const int t = threadIdx.x;
    const int w = t >> 5, lane = t & 31;
    const int lq = lane >> 2, lr = lane & 3;
    const int cw = (w & 3) * 32, nw = (w >> 2) * 64;

    for (int i = t; i < 16384; i += 256) {
        int c = i >> 7, d = i & 127;
        os_[CO_AS + c * 132 + d] = f32_tf32(g_e[((b * C + c) << 7) + d]);
    }
    for (int i = t; i < 16384; i += 256) {
        int d = i >> 7, n = i & 127;
        os_[CO_FS + d * 136 + n] = f32_tf32(g_y[((b * C + d) << 12) + nb + n]);
    }
    __syncthreads();

    float acc[2][8][4];
#pragma unroll
    for (int ct = 0; ct < 2; ct++)
#pragma unroll
        for (int nt = 0; nt < 8; nt++)
#pragma unroll
            for (int i = 0; i < 4; i++) acc[ct][nt][i] = 0.f;

#pragma unroll
    for (int ks = 0; ks < 16; ks++) {
        const int k = ks * 8;
        uint32_t a[2][4];
#pragma unroll
        for (int ct = 0; ct < 2; ct++) {
            int r = (cw + ct * 16 + lq) * 132 + k + lr;
            a[ct][0] = os_[CO_AS + r];
            a[ct][1] = os_[CO_AS + r + 8 * 132];
            a[ct][2] = os_[CO_AS + r + 4];
            a[ct][3] = os_[CO_AS + r + 8 * 132 + 4];
        }
#pragma unroll
        for (int nt = 0; nt < 8; nt++) {
            uint32_t b0 = os_[CO_FS + (k + lr) * 136 + nw + nt * 8 + lq];
            uint32_t b1 = os_[CO_FS + (k + lr + 4) * 136 + nw + nt * 8 + lq];
#pragma unroll
            for (int ct = 0; ct < 2; ct++)
                mma_tf32(acc[ct][nt], a[ct], b0, b1);
        }
    }

    const float g = gca[0];
#pragma unroll
    for (int ct = 0; ct < 2; ct++) {
#pragma unroll
        for (int rr = 0; rr < 2; rr++) {
            int c = cw + ct * 16 + lq + rr * 8;
            float* row = &out[((b * C + c) << 12) + nb + nw];
#pragma unroll
            for (int nt = 0; nt < 8; nt++) {
                int n = nt * 8 + lr * 2;
                float2* p = (float2*)&row[n];
                float2 cur = *p;
                cur.x += g * acc[ct][nt][rr * 2];
                cur.y += g * acc[ct][nt][rr * 2 + 1];
                *p = cur;
            }
        }
    }
}

// ---------------- K8: PAM: m-tile 128, n-chunk 64, 3-stage cp.async ----------
#define P_QS 0                       // q^T [m][qc] 128x20 = 2560
#define P_KS 2560                    // k [qc][n]  3 x 16x68 = 3264
#define P_VS 5824                    // v [c][n]   3 x 128x68 = 26112
#define P_SN 31936                   // S^T [n][m] 64x136 = 8704
#define P_WORDS 40640

__global__ __launch_bounds__(256, 1)
void pam_mma_kernel(const float* __restrict__ gpa, float* __restrict__ out) {
    extern __shared__ uint32_t ps[];
    const int b = blockIdx.y, m0 = blockIdx.x * 128;
    const int t = threadIdx.x;
    const int w = t >> 5, lane = t & 31;
    const int lq = lane >> 2, lr = lane & 3;
    const uint32_t sbase = (uint32_t)__cvta_generic_to_shared(ps);

    for (int i = t; i < 2048; i += 256) {
        int qc = i >> 7, m = i & 127;
        ps[P_QS + m * 20 + qc] = g_q[((b * CQK + qc) << 12) + m0 + m];
    }

    const int krow = t >> 4, kc4 = (t & 15) * 4;
    const uint32_t kdst = sbase + (P_KS + krow * 68 + kc4) * 4;
    const uint32_t* kgsrc = &g_k[((b * CQK + krow) << 12) + kc4];
    const uint32_t vdst = sbase + (P_VS + krow * 68 + kc4) * 4;
    const uint32_t* vgsrc = &g_v[((b * C + krow) << 12) + kc4];

    // prologue: chunks 0 and 1 into slots 0, 1 (separate groups)
    cp16(kdst, kgsrc);
#pragma unroll
    for (int p = 0; p < 8; p++)
        cp16(vdst + p * 16 * 68 * 4, vgsrc + (p << 16));
    cp_commit();
    cp16(kdst + 1088 * 4, kgsrc + 64);
#pragma unroll
    for (int p = 0; p < 8; p++)
        cp16(vdst + (8704 + p * 16 * 68) * 4, vgsrc + (p << 16) + 64);
    cp_commit();

    __syncthreads();   // q^T visible to all warps before fragment hoist

    uint32_t aq[2][4];
#pragma unroll
    for (int ks = 0; ks < 2; ks++) {
        int r = w * 16 + lq, c = ks * 8 + lr;
        aq[ks][0] = ps[P_QS + r * 20 + c];
        aq[ks][1] = ps[P_QS + (r + 8) * 20 + c];
        aq[ks][2] = ps[P_QS + r * 20 + c + 4];
        aq[ks][3] = ps[P_QS + (r + 8) * 20 + c + 4];
    }

    const int cw = (w & 3) * 32, mw = (w >> 2) * 64;
    float acc[2][8][4];
#pragma unroll
    for (int ct = 0; ct < 2; ct++)
#pragma unroll
        for (int mt = 0; mt < 8; mt++)
#pragma unroll
            for (int i = 0; i < 4; i++) acc[ct][mt][i] = 0.f;

    int sc = 0, sp = 2;    // current slot, prefetch slot ((ch+2)%3)
#pragma unroll 1
    for (int ch = 0; ch < 64; ch++) {
        cp_wait<1>();      // chunk ch landed (ch+1 may still be in flight)
        __syncthreads();   // data visibility + all warps past GEMM2(ch-1)

        // prefetch chunk ch+2 into slot sp (last read by GEMM2(ch-1))
        if (ch + 2 < 64) {
            const int n2 = (ch + 2) * 64;
            cp16(kdst + sp * 1088 * 4, kgsrc + n2);
#pragma unroll
            for (int p = 0; p < 8; p++)
                cp16(vdst + (sp * 8704 + p * 16 * 68) * 4, vgsrc + (p << 16) + n2);
        }
        cp_commit();       // always commit (possibly empty) to keep group count

        const uint32_t* ksb = ps + P_KS + sc * 1088;
        const uint32_t* vsb = ps + P_VS + sc * 8704;

        // E phase: warp rows [16w, 16w+16) x 64 n
        float e[8][4];
#pragma unroll
        for (int ni = 0; ni < 8; ni++) {
#pragma unroll
            for (int i = 0; i < 4; i++) e[ni][i] = 0.f;
#pragma unroll
            for (int ks = 0; ks < 2; ks++) {
                uint32_t b0 = ksb[(ks * 8 + lr) * 68 + ni * 8 + lq];
                uint32_t b1 = ksb[(ks * 8 + lr + 4) * 68 + ni * 8 + lq];
                mma_tf32(e[ni], aq[ks], b0, b1);
            }
        }
        {
            int m = w * 16 + lq;
#pragma unroll
            for (int ni = 0; ni < 8; ni++) {
                int n = ni * 8 + lr * 2;
                ps[P_SN + n * 136 + m]           = f32_tf32(tanh_ap(e[ni][0]));
                ps[P_SN + (n + 1) * 136 + m]     = f32_tf32(tanh_ap(e[ni][1]));
                ps[P_SN + n * 136 + m + 8]       = f32_tf32(tanh_ap(e[ni][2]));
                ps[P_SN + (n + 1) * 136 + m + 8] = f32_tf32(tanh_ap(e[ni][3]));
            }
        }
        __syncthreads();   // S^T exchange

        // GEMM2: acc[32c x 64m] += v * S^T
#pragma unroll
        for (int ks = 0; ks < 8; ks++) {
            const int k = ks * 8;
            uint32_t a[2][4], bb[8][2];
#pragma unroll
            for (int ct = 0; ct < 2; ct++) {
                int r = (cw + ct * 16 + lq) * 68 + k + lr;
                a[ct][0] = vsb[r];
                a[ct][1] = vsb[r + 8 * 68];
                a[ct][2] = vsb[r + 4];
                a[ct][3] = vsb[r + 8 * 68 + 4];
            }
#pragma unroll
            for (int mt = 0; mt < 8; mt++) {
                int c = mw + mt * 8 + lq;
                bb[mt][0] = ps[P_SN + (k + lr) * 136 + c];
                bb[mt][1] = ps[P_SN + (k + lr + 4) * 136 + c];
            }
#pragma unroll
            for (int ct = 0; ct < 2; ct++)
#pragma unroll
                for (int mt = 0; mt < 8; mt++)
                    mma_tf32(acc[ct][mt], a[ct], bb[mt][0], bb[mt][1]);
        }

        sc = (sc == 2) ? 0 : sc + 1;
        sp = (sp == 2) ? 0 : sp + 1;
    }

    const float g = gpa[0];
#pragma unroll
    for (int ct = 0; ct < 2; ct++) {
#pragma unroll
        for (int rr = 0; rr < 2; rr++) {
            int c = cw + ct * 16 + lq + rr * 8;
            float* row = &out[((b * C + c) << 12) + m0 + mw];
#pragma unroll
            for (int mt = 0; mt < 8; mt++) {
                int m = mt * 8 + lr * 2;
                float2* p = (float2*)&row[m];
                float2 cur = *p;
                cur.x += g * acc[ct][mt][rr * 2];
                cur.y += g * acc[ct][mt][rr * 2 + 1];
                *p = cur;
            }
        }
    }
}

// ---------------- launch ----------------
extern "C" void kernel_launch(void* const* d_in, const int* in_sizes, int n_in,
                              void* d_out, int out_size) {
    const float* x       = (const float*)d_in[0];
    const float* conv_w  = (const float*)d_in[1];
    const float* bn_g    = (const float*)d_in[2];
    const float* bn_b    = (const float*)d_in[3];
    const float* q_w     = (const float*)d_in[4];
    const float* q_b     = (const float*)d_in[5];
    const float* k_w     = (const float*)d_in[6];
    const float* k_b     = (const float*)d_in[7];
    const float* v_w     = (const float*)d_in[8];
    const float* v_b     = (const float*)d_in[9];
    const float* gca     = (const float*)d_in[10];
    const float* gpa     = (const float*)d_in[11];
    float* out = (float*)d_out;

    cudaFuncSetAttribute(conv_tc_kernel, cudaFuncAttributeMaxDynamicSharedMemorySize,
                         CONV_SMEM_WORDS * 4);
    cudaFuncSetAttribute(pam_mma_kernel, cudaFuncAttributeMaxDynamicSharedMemorySize,
                         P_WORDS * 4);
    cudaFuncSetAttribute(qkv_mma_kernel, cudaFuncAttributeMaxDynamicSharedMemorySize,
                         QK_WORDS * 4);
    cudaFuncSetAttribute(cam_energy_mma_kernel, cudaFuncAttributeMaxDynamicSharedMemorySize,
                         CE_WORDS * 4);
    cudaFuncSetAttribute(cam_out_mma_kernel, cudaFuncAttributeMaxDynamicSharedMemorySize,
                         CO_WORDS * 4);

    wprep_kernel<<<1152, 256>>>(conv_w);
    conv_tc_kernel<<<dim3(64, B), 256, CONV_SMEM_WORDS * 4>>>(x);
    bnstats1_kernel<<<512, 256>>>();
    bnstats2_kernel<<<1, 128>>>(bn_g, bn_b);
    bnrelu_kernel<<<2048, 256>>>(out);
    qkv_mma_kernel<<<dim3(64, B), 320, QK_WORDS * 4>>>(q_w, q_b, k_w, k_b, v_w, v_b);
    cam_energy_mma_kernel<<<dim3(ESPLIT, B), 256, CE_WORDS * 4>>>();
    cam_reduce_kernel<<<dim3(C, B), 128>>>();
    cam_out_mma_kernel<<<dim3(32, B), 256, CO_WORDS * 4>>>(gca, out);
    pam_mma_kernel<<<dim3(32, B), 256, P_WORDS * 4>>>(gpa, out);
}